// round 12
// baseline (speedup 1.0000x reference)
#include <cuda_runtime.h>
#include <cuda_fp16.h>
#include <cstdint>

#define B_   16
#define N_   16384
#define C_   288
#define S_   256
#define KS   16
#define CIN0 291
#define SK4  4096
#define KPAD 320
#define MPAD 384
#define KT_  5
#define MLP_SMEM (3*32768 + 1024)

// ---------------- scratch ----------------
__device__ float g_newxyz[B_*S_*3];
__device__ int   g_idx[B_*S_*KS];
__device__ __align__(256) __half g_x0[(size_t)B_*SK4*KPAD];
__device__ __align__(256) __half g_x1[(size_t)B_*SK4*KPAD];
__device__ __align__(256) __half g_w[3*MPAD*KPAD];

// ---------------- helpers ----------------
__device__ __forceinline__ uint32_t smem_u32(const void* p) {
    uint32_t a;
    asm("{ .reg .u64 t; cvta.to.shared.u64 t, %1; cvt.u32.u64 %0, t; }" : "=r"(a) : "l"(p));
    return a;
}
#define CP_COMMIT() asm volatile("cp.async.commit_group;" ::: "memory")
#define CP_WAIT(n)  asm volatile("cp.async.wait_group %0;" :: "n"(n) : "memory")
__device__ __forceinline__ void cp16(uint32_t s, const void* g) {
    asm volatile("cp.async.cg.shared.global [%0], [%1], 16;" :: "r"(s), "l"(g) : "memory");
}
__device__ __forceinline__ void ldsm4(uint32_t* r, uint32_t a) {
    asm volatile("ldmatrix.sync.aligned.m8n8.x4.shared.b16 {%0,%1,%2,%3}, [%4];"
        : "=r"(r[0]),"=r"(r[1]),"=r"(r[2]),"=r"(r[3]) : "r"(a));
}
__device__ __forceinline__ void ldsm2(uint32_t* r, uint32_t a) {
    asm volatile("ldmatrix.sync.aligned.m8n8.x2.shared.b16 {%0,%1}, [%2];"
        : "=r"(r[0]),"=r"(r[1]) : "r"(a));
}
__device__ __forceinline__ void mma16816(float* c, const uint32_t* a, const uint32_t* b) {
    asm volatile("mma.sync.aligned.m16n8k16.row.col.f32.f16.f16.f32 "
        "{%0,%1,%2,%3}, {%4,%5,%6,%7}, {%8,%9}, {%0,%1,%2,%3};"
        : "+f"(c[0]),"+f"(c[1]),"+f"(c[2]),"+f"(c[3])
        : "r"(a[0]),"r"(a[1]),"r"(a[2]),"r"(a[3]), "r"(b[0]),"r"(b[1]));
}
__device__ __forceinline__ uint32_t sw128(uint32_t off) {
    return off ^ ((off >> 3) & 0x70);
}
// packed f32x2 (rn per lane, bit-identical to scalar __fmul_rn/__fadd_rn)
__device__ __forceinline__ uint64_t sub2(uint64_t a, uint64_t b) {
    uint64_t d; asm("sub.rn.f32x2 %0, %1, %2;" : "=l"(d) : "l"(a), "l"(b)); return d;
}
__device__ __forceinline__ uint64_t mul2(uint64_t a, uint64_t b) {
    uint64_t d; asm("mul.rn.f32x2 %0, %1, %2;" : "=l"(d) : "l"(a), "l"(b)); return d;
}
__device__ __forceinline__ uint64_t add2(uint64_t a, uint64_t b) {
    uint64_t d; asm("add.rn.f32x2 %0, %1, %2;" : "=l"(d) : "l"(a), "l"(b)); return d;
}
__device__ __forceinline__ uint64_t pack2(float lo, float hi) {
    uint64_t d; asm("mov.b64 %0, {%1, %2};" : "=l"(d) : "f"(lo), "f"(hi)); return d;
}
__device__ __forceinline__ void unpack2(uint64_t v, float& lo, float& hi) {
    asm("mov.b64 {%0, %1}, %2;" : "=f"(lo), "=f"(hi) : "l"(v));
}

// ---------------- FPS: f32x2 distance, deferred argmax, bit-exact ----------------
extern __shared__ float fps_sm[];
__global__ void __launch_bounds__(1024) fps_kernel(const float* __restrict__ xyz,
                                                   float* __restrict__ out_xyz,
                                                   float* __restrict__ out_inds)
{
    float* sx = fps_sm;
    float* sy = fps_sm + N_;
    float* sz = fps_sm + 2*N_;
    __shared__ float r_d[32];
    __shared__ int   r_i[32];
    __shared__ float s_c[3];
    __shared__ int   s_ci;

    int b = blockIdx.x, tid = threadIdx.x;
    const float* xb = xyz + (long)b*N_*3;
    for (int i = tid; i < N_; i += 1024) {
        sx[i] = xb[3*i];
        sy[i] = xb[3*i+1];
        sz[i] = xb[3*i+2];
    }
    float dist[16];
#pragma unroll
    for (int j = 0; j < 16; j++) dist[j] = 1e10f;
    if (tid == 0) s_ci = 0;
    __syncthreads();
    if (tid == 0) { s_c[0] = sx[0]; s_c[1] = sy[0]; s_c[2] = sz[0]; }
    __syncthreads();

    const ulonglong2* sx4 = (const ulonglong2*)sx;
    const ulonglong2* sy4 = (const ulonglong2*)sy;
    const ulonglong2* sz4 = (const ulonglong2*)sz;
    int lane = tid & 31, wid = tid >> 5;

    for (int t = 0; t < S_; t++) {
        float cx = s_c[0], cy = s_c[1], cz = s_c[2];
        if (tid == 0) {
            int ci = s_ci;
            out_inds[b*S_ + t] = (float)ci;
            out_xyz[(b*S_ + t)*3 + 0] = cx;
            out_xyz[(b*S_ + t)*3 + 1] = cy;
            out_xyz[(b*S_ + t)*3 + 2] = cz;
            g_newxyz[(b*S_ + t)*3 + 0] = cx;
            g_newxyz[(b*S_ + t)*3 + 1] = cy;
            g_newxyz[(b*S_ + t)*3 + 2] = cz;
        }
        uint64_t cx2 = pack2(cx, cx), cy2 = pack2(cy, cy), cz2 = pack2(cz, cz);
        float bd = -1.0f;
#pragma unroll
        for (int j = 0; j < 4; j++) {
            ulonglong2 xv = sx4[tid*4 + j];
            ulonglong2 yv = sy4[tid*4 + j];
            ulonglong2 zv = sz4[tid*4 + j];
            uint64_t dxa = sub2(xv.x, cx2), dxb = sub2(xv.y, cx2);
            uint64_t dya = sub2(yv.x, cy2), dyb = sub2(yv.y, cy2);
            uint64_t dza = sub2(zv.x, cz2), dzb = sub2(zv.y, cz2);
            uint64_t sa = add2(add2(mul2(dxa,dxa), mul2(dya,dya)), mul2(dza,dza));
            uint64_t sb = add2(add2(mul2(dxb,dxb), mul2(dyb,dyb)), mul2(dzb,dzb));
            float d0, d1, d2, d3;
            unpack2(sa, d0, d1);
            unpack2(sb, d2, d3);
            float m0 = fminf(dist[4*j+0], d0);
            float m1 = fminf(dist[4*j+1], d1);
            float m2 = fminf(dist[4*j+2], d2);
            float m3 = fminf(dist[4*j+3], d3);
            dist[4*j+0] = m0; dist[4*j+1] = m1; dist[4*j+2] = m2; dist[4*j+3] = m3;
            bd = fmaxf(bd, fmaxf(fmaxf(m0, m1), fmaxf(m2, m3)));
        }
        int bi = 0;
#pragma unroll
        for (int j = 15; j >= 0; j--)
            if (dist[j] == bd) bi = tid*16 + j;
#pragma unroll
        for (int off = 16; off; off >>= 1) {
            float od = __shfl_down_sync(0xffffffffu, bd, off);
            int   oi = __shfl_down_sync(0xffffffffu, bi, off);
            if (od > bd || (od == bd && oi < bi)) { bd = od; bi = oi; }
        }
        if (lane == 0) { r_d[wid] = bd; r_i[wid] = bi; }
        __syncthreads();
        if (wid == 0) {
            bd = r_d[lane]; bi = r_i[lane];
#pragma unroll
            for (int off = 16; off; off >>= 1) {
                float od = __shfl_down_sync(0xffffffffu, bd, off);
                int   oi = __shfl_down_sync(0xffffffffu, bi, off);
                if (od > bd || (od == bd && oi < bi)) { bd = od; bi = oi; }
            }
            if (lane == 0) { s_ci = bi; s_c[0] = sx[bi]; s_c[1] = sy[bi]; s_c[2] = sz[bi]; }
        }
        __syncthreads();
    }
}

// ---------------- ball query ----------------
__global__ void ballq_kernel(const float* __restrict__ xyz)
{
    int gw   = (blockIdx.x * blockDim.x + threadIdx.x) >> 5;
    int lane = threadIdx.x & 31;
    int b = gw >> 8, s = gw & 255;
    const float* xb = xyz + (long)b*N_*3;
    float cx = g_newxyz[(b*S_+s)*3 + 0];
    float cy = g_newxyz[(b*S_+s)*3 + 1];
    float cz = g_newxyz[(b*S_+s)*3 + 2];
    int* out = g_idx + (b*S_+s)*KS;
    int count = 0, first = -1;
    for (int base = 0; base < N_; base += 32) {
        int p = base + lane;
        float dx = xb[3*p] - cx, dy = xb[3*p+1] - cy, dz = xb[3*p+2] - cz;
        float d = __fadd_rn(__fadd_rn(__fmul_rn(dx,dx), __fmul_rn(dy,dy)), __fmul_rn(dz,dz));
        bool in = d < 0.09f;
        unsigned mask = __ballot_sync(0xffffffffu, in);
        if (first < 0 && mask) first = base + __ffs(mask) - 1;
        if (in) {
            int slot = count + __popc(mask & ((1u << lane) - 1u));
            if (slot < KS) out[slot] = p;
        }
        count += __popc(mask);
        if (count >= KS) break;
    }
    if (lane < KS && lane >= count) out[lane] = first;
}

// ---------------- gather -> x0 [n][k] fp16, zero-padded K ----------------
__global__ void gather_kernel(const float* __restrict__ xyz, const float* __restrict__ feat)
{
    int w    = (blockIdx.x * blockDim.x + threadIdx.x) >> 5;
    int lane = threadIdx.x & 31;
    int b = w >> 12, n = w & 4095;
    int id = g_idx[b*SK4 + n];
    int s = n >> 4;
    size_t orow = ((size_t)b*SK4 + n) * KPAD;
    const float* fb = feat + (size_t)b*C_*N_ + id;

    float v[10];
#pragma unroll
    for (int it = 0; it < 10; it++) {
        int c = it*32 + lane;
        float val = 0.0f;
        if (it == 0 && lane < 3) {
            val = (xyz[((size_t)b*N_ + id)*3 + c] - g_newxyz[(b*S_+s)*3 + c]) / 0.3f;
        } else if (c < CIN0) {
            val = __ldg(fb + (size_t)(c-3)*N_);
        }
        v[it] = val;
    }
#pragma unroll
    for (int it = 0; it < 10; it++) {
        g_x0[orow + it*32 + lane] = __float2half_rn(v[it]);
    }
}

// ---------------- weight prep ----------------
__global__ void wprep_kernel(const float* __restrict__ W0, const float* __restrict__ W1,
                             const float* __restrict__ W2)
{
    int i = blockIdx.x*256 + threadIdx.x;
    if (i >= 3*MPAD*KPAD) return;
    int l = i / (MPAD*KPAD);
    int r = i % (MPAD*KPAD);
    int m = r / KPAD, k = r % KPAD;
    int cin = (l == 0) ? CIN0 : C_;
    float w = 0.0f;
    if (m < C_ && k < cin) {
        const float* W = (l == 0) ? W0 : ((l == 1) ? W1 : W2);
        w = W[m*cin + k];
    }
    g_w[i] = __float2half_rn(w);
}

// ---------------- fp16 mma GEMM + BN/ReLU (+max), occ 1, 3-stage pipeline ----------------
// grid (32 ntiles, 3 mtiles, 16 batches), 256 threads (8 warps: 2m x 4n of 64x32)
__global__ void __launch_bounds__(256, 1) mlp_mma(
    const __half* __restrict__ W, const __half* __restrict__ X,
    __half* __restrict__ O, float* __restrict__ Omax,
    const float* __restrict__ gg, const float* __restrict__ bbp,
    const float* __restrict__ mmp, const float* __restrict__ vvp, int maxmode)
{
    extern __shared__ char dsm_raw[];
    __shared__ float s_sc[128], s_sh[128];

    uint32_t raw = smem_u32(dsm_raw);
    uint32_t dsm = (raw + 1023u) & ~1023u;
    char* dptr = dsm_raw + (dsm - raw);

    int tid = threadIdx.x, lane = tid & 31, wid = tid >> 5;
    int wm = wid & 1, wn = wid >> 1;
    int n0 = blockIdx.x * 128, m0 = blockIdx.y * 128, b = blockIdx.z;

    if (tid < 128) {
        int o = m0 + tid;
        float sc = 0.0f, sh = 0.0f;
        if (o < C_) {
            sc = gg[o] * rsqrtf(vvp[o] + 1e-5f);
            sh = bbp[o] - mmp[o]*sc;
        }
        s_sc[tid] = sc; s_sh[tid] = sh;
    }

    const char* aSrc = (const char*)(W + (size_t)m0 * KPAD);
    const char* bSrc = (const char*)(X + ((size_t)b*SK4 + n0) * KPAD);

    // stage: 2 tiles x (128 rows x 128B) = 32KB; 3 stages
    auto load_stage = [&](int kt, int s) {
        uint32_t sb = dsm + s*32768;
        int k0b = kt * 128;
        const char* srcs[2] = { aSrc, bSrc };
#pragma unroll
        for (int t = 0; t < 2; t++) {
            uint32_t tb = sb + t*16384;
            const char* g = srcs[t] + k0b;
#pragma unroll
            for (int i = 0; i < 4; i++) {
                int idx = tid + i*256;
                int r = idx >> 3, c = idx & 7;
                cp16(tb + sw128(r*128 + c*16), g + (size_t)r*(KPAD*2) + c*16);
            }
        }
        CP_COMMIT();
    };

    load_stage(0, 0);
    load_stage(1, 1);
    load_stage(2, 2);

    float acc[4][4][4];
#pragma unroll
    for (int i = 0; i < 4; i++)
#pragma unroll
        for (int j = 0; j < 4; j++)
#pragma unroll
            for (int r = 0; r < 4; r++) acc[i][j][r] = 0.0f;

    __syncthreads();  // s_sc ready

#pragma unroll 1
    for (int kt = 0; kt < KT_; kt++) {
        int s = kt % 3;
        if (kt <= KT_ - 3)      CP_WAIT(2);
        else if (kt == KT_ - 2) CP_WAIT(1);
        else                    CP_WAIT(0);
        __syncthreads();
        uint32_t sb = dsm + s*32768;
        uint32_t tA = sb, tB = sb + 16384;
#pragma unroll
        for (int ks = 0; ks < 4; ks++) {
            uint32_t bh[4][2];
#pragma unroll
            for (int j = 0; j < 4; j++) {
                uint32_t o = sw128((wn*32 + j*8 + (lane & 7))*128 + ((lane >> 3) & 1)*16 + ks*32);
                ldsm2(bh[j], tB + o);
            }
#pragma unroll
            for (int i = 0; i < 4; i++) {
                uint32_t ah[4];
                uint32_t o = sw128((wm*64 + i*16 + (lane & 15))*128 + (lane >> 4)*16 + ks*32);
                ldsm4(ah, tA + o);
#pragma unroll
                for (int j = 0; j < 4; j++)
                    mma16816(acc[i][j], ah, bh[j]);
            }
        }
        if (kt + 3 < KT_) {
            __syncthreads();
            load_stage(kt + 3, s);
        }
    }

    // ---------------- epilogue ----------------
    if (maxmode) {
#pragma unroll
        for (int i = 0; i < 4; i++) {
#pragma unroll
            for (int r = 0; r < 2; r++) {
                int ml = wm*64 + i*16 + (lane >> 2) + r*8;
                float sc = s_sc[ml], sh = s_sh[ml];
#pragma unroll
                for (int g = 0; g < 2; g++) {
                    float mx = 0.0f;
#pragma unroll
                    for (int jj = 0; jj < 2; jj++) {
                        int j = g*2 + jj;
                        float v0 = fmaxf(fmaf(acc[i][j][r*2],   sc, sh), 0.0f);
                        float v1 = fmaxf(fmaf(acc[i][j][r*2+1], sc, sh), 0.0f);
                        mx = fmaxf(mx, fmaxf(v0, v1));
                    }
                    mx = fmaxf(mx, __shfl_xor_sync(0xffffffffu, mx, 1));
                    mx = fmaxf(mx, __shfl_xor_sync(0xffffffffu, mx, 2));
                    int o = m0 + ml;
                    if ((lane & 3) == 0 && o < C_) {
                        int sgrp = (n0 >> 4) + wn*2 + g;
                        Omax[((size_t)b*C_ + o)*S_ + sgrp] = mx;
                    }
                }
            }
        }
    } else {
        // transpose+store in two half-m chunks via 64x132 smem float buffer
        float* smt = (float*)dptr;
#pragma unroll 1
        for (int h = 0; h < 2; h++) {
            __syncthreads();
            if (wm == h) {
#pragma unroll
                for (int i = 0; i < 4; i++) {
#pragma unroll
                    for (int r = 0; r < 2; r++) {
                        int ml = i*16 + (lane >> 2) + r*8;   // 0..63
                        float sc = s_sc[h*64 + ml], sh = s_sh[h*64 + ml];
#pragma unroll
                        for (int j = 0; j < 4; j++) {
                            int nl = wn*32 + j*8 + (lane & 3)*2;
                            float v0 = fmaxf(fmaf(acc[i][j][r*2],   sc, sh), 0.0f);
                            float v1 = fmaxf(fmaf(acc[i][j][r*2+1], sc, sh), 0.0f);
                            smt[ml*132 + nl]     = v0;
                            smt[ml*132 + nl + 1] = v1;
                        }
                    }
                }
            }
            __syncthreads();
            int n = tid >> 1, half = tid & 1;
            int colg = m0 + h*64 + half*32;
            if (colg < KPAD) {
                size_t doff = ((size_t)b*SK4 + n0 + n)*KPAD + colg;
                uint32_t p[8];
#pragma unroll
                for (int e = 0; e < 8; e++) {
                    float v0 = smt[(half*32 + 2*e)*132 + n];
                    float v1 = smt[(half*32 + 2*e + 1)*132 + n];
                    __half2 hv = __floats2half2_rn(v0, v1);
                    p[e] = *(uint32_t*)&hv;
                }
                *(uint4*)(O + doff)     = make_uint4(p[0], p[1], p[2], p[3]);
                *(uint4*)(O + doff + 8) = make_uint4(p[4], p[5], p[6], p[7]);
                uint32_t q[8];
#pragma unroll
                for (int e = 0; e < 8; e++) {
                    float v0 = smt[(half*32 + 16 + 2*e)*132 + n];
                    float v1 = smt[(half*32 + 16 + 2*e + 1)*132 + n];
                    __half2 hv = __floats2half2_rn(v0, v1);
                    q[e] = *(uint32_t*)&hv;
                }
                *(uint4*)(O + doff + 16) = make_uint4(q[0], q[1], q[2], q[3]);
                *(uint4*)(O + doff + 24) = make_uint4(q[4], q[5], q[6], q[7]);
            }
        }
    }
}

// ---------------- launch ----------------
extern "C" void kernel_launch(void* const* d_in, const int* in_sizes, int n_in,
                              void* d_out, int out_size)
{
    const float* xyz  = (const float*)d_in[0];
    const float* feat = (const float*)d_in[1];
    const float* W0 = (const float*)d_in[2];
    const float* g0 = (const float*)d_in[3];
    const float* b0 = (const float*)d_in[4];
    const float* m0 = (const float*)d_in[5];
    const float* v0 = (const float*)d_in[6];
    const float* W1 = (const float*)d_in[7];
    const float* g1 = (const float*)d_in[8];
    const float* b1 = (const float*)d_in[9];
    const float* m1 = (const float*)d_in[10];
    const float* v1 = (const float*)d_in[11];
    const float* W2 = (const float*)d_in[12];
    const float* g2 = (const float*)d_in[13];
    const float* b2 = (const float*)d_in[14];
    const float* m2 = (const float*)d_in[15];
    const float* v2 = (const float*)d_in[16];

    float* out      = (float*)d_out;
    float* out_xyz  = out;
    float* out_feat = out + B_*S_*3;
    float* out_inds = out + B_*S_*3 + (long)B_*C_*S_;

    cudaFuncSetAttribute(fps_kernel, cudaFuncAttributeMaxDynamicSharedMemorySize,
                         3*N_*(int)sizeof(float));
    cudaFuncSetAttribute(mlp_mma, cudaFuncAttributeMaxDynamicSharedMemorySize, MLP_SMEM);

    wprep_kernel<<<(3*MPAD*KPAD + 255)/256, 256>>>(W0, W1, W2);
    fps_kernel<<<B_, 1024, 3*N_*sizeof(float)>>>(xyz, out_xyz, out_inds);
    ballq_kernel<<<512, 256>>>(xyz);
    gather_kernel<<<8192, 256>>>(xyz, feat);

    __half *w, *x0, *x1;
    cudaGetSymbolAddress((void**)&w,  g_w);
    cudaGetSymbolAddress((void**)&x0, g_x0);
    cudaGetSymbolAddress((void**)&x1, g_x1);

    dim3 grid(32, 3, 16);
    const int L = MPAD*KPAD;
    mlp_mma<<<grid, 256, MLP_SMEM>>>(w,       x0, x1, nullptr, g0, b0, m0, v0, 0);
    mlp_mma<<<grid, 256, MLP_SMEM>>>(w + L,   x1, x0, nullptr, g1, b1, m1, v1, 0);
    mlp_mma<<<grid, 256, MLP_SMEM>>>(w + 2*L, x0, nullptr, out_feat, g2, b2, m2, v2, 1);
}

// round 14
// speedup vs baseline: 1.7993x; 1.7993x over previous
#include <cuda_runtime.h>
#include <cuda_fp16.h>
#include <cstdint>

#define B_   16
#define N_   16384
#define C_   288
#define S_   256
#define KS   16
#define CIN0 291
#define SK4  4096
#define KPAD 320
#define MPAD 384
#define KT_  5
#define MLP_SMEM (2*32768 + 1024)

// ---------------- scratch ----------------
__device__ float g_newxyz[B_*S_*3];
__device__ int   g_idx[B_*S_*KS];
__device__ __align__(256) __half g_x0[(size_t)B_*SK4*KPAD];
__device__ __align__(256) __half g_x1[(size_t)B_*SK4*KPAD];
__device__ __align__(256) __half g_w[3*MPAD*KPAD];

// ---------------- helpers ----------------
__device__ __forceinline__ uint32_t smem_u32(const void* p) {
    uint32_t a;
    asm("{ .reg .u64 t; cvta.to.shared.u64 t, %1; cvt.u32.u64 %0, t; }" : "=r"(a) : "l"(p));
    return a;
}
#define CP_COMMIT() asm volatile("cp.async.commit_group;" ::: "memory")
#define CP_WAIT(n)  asm volatile("cp.async.wait_group %0;" :: "n"(n) : "memory")
__device__ __forceinline__ void cp16(uint32_t s, const void* g) {
    asm volatile("cp.async.cg.shared.global [%0], [%1], 16;" :: "r"(s), "l"(g) : "memory");
}
__device__ __forceinline__ void ldsm4(uint32_t* r, uint32_t a) {
    asm volatile("ldmatrix.sync.aligned.m8n8.x4.shared.b16 {%0,%1,%2,%3}, [%4];"
        : "=r"(r[0]),"=r"(r[1]),"=r"(r[2]),"=r"(r[3]) : "r"(a));
}
__device__ __forceinline__ void ldsm2(uint32_t* r, uint32_t a) {
    asm volatile("ldmatrix.sync.aligned.m8n8.x2.shared.b16 {%0,%1}, [%2];"
        : "=r"(r[0]),"=r"(r[1]) : "r"(a));
}
__device__ __forceinline__ void mma16816(float* c, const uint32_t* a, const uint32_t* b) {
    asm volatile("mma.sync.aligned.m16n8k16.row.col.f32.f16.f16.f32 "
        "{%0,%1,%2,%3}, {%4,%5,%6,%7}, {%8,%9}, {%0,%1,%2,%3};"
        : "+f"(c[0]),"+f"(c[1]),"+f"(c[2]),"+f"(c[3])
        : "r"(a[0]),"r"(a[1]),"r"(a[2]),"r"(a[3]), "r"(b[0]),"r"(b[1]));
}
__device__ __forceinline__ uint32_t sw128(uint32_t off) {
    return off ^ ((off >> 3) & 0x70);
}

// ---------------- FPS: scalar, conflict-free, bit-exact (R4 version) ----------------
extern __shared__ float fps_sm[];
__global__ void __launch_bounds__(1024) fps_kernel(const float* __restrict__ xyz,
                                                   float* __restrict__ out_xyz,
                                                   float* __restrict__ out_inds)
{
    float* sx = fps_sm;
    float* sy = fps_sm + N_;
    float* sz = fps_sm + 2*N_;
    __shared__ float r_d[32];
    __shared__ int   r_i[32];
    __shared__ float s_c[3];
    __shared__ int   s_ci;

    int b = blockIdx.x, tid = threadIdx.x;
    const float* xb = xyz + (long)b*N_*3;
    for (int i = tid; i < N_; i += 1024) {
        sx[i] = xb[3*i];
        sy[i] = xb[3*i+1];
        sz[i] = xb[3*i+2];
    }
    float dist[16];
#pragma unroll
    for (int j = 0; j < 16; j++) dist[j] = 1e10f;
    if (tid == 0) s_ci = 0;
    __syncthreads();
    if (tid == 0) { s_c[0] = sx[0]; s_c[1] = sy[0]; s_c[2] = sz[0]; }
    __syncthreads();

    int lane = tid & 31, wid = tid >> 5;
    for (int t = 0; t < S_; t++) {
        float cx = s_c[0], cy = s_c[1], cz = s_c[2];
        if (tid == 0) {
            int ci = s_ci;
            out_inds[b*S_ + t] = (float)ci;
            out_xyz[(b*S_ + t)*3 + 0] = cx;
            out_xyz[(b*S_ + t)*3 + 1] = cy;
            out_xyz[(b*S_ + t)*3 + 2] = cz;
            g_newxyz[(b*S_ + t)*3 + 0] = cx;
            g_newxyz[(b*S_ + t)*3 + 1] = cy;
            g_newxyz[(b*S_ + t)*3 + 2] = cz;
        }
        float bd = -1.0f; int bi = 0;
#pragma unroll
        for (int j = 0; j < 16; j++) {
            int p = j*1024 + tid;
            float dx = sx[p] - cx, dy = sy[p] - cy, dz = sz[p] - cz;
            float d = __fadd_rn(__fadd_rn(__fmul_rn(dx,dx), __fmul_rn(dy,dy)), __fmul_rn(dz,dz));
            float dm = fminf(dist[j], d);
            dist[j] = dm;
            if (dm > bd) { bd = dm; bi = p; }
        }
#pragma unroll
        for (int off = 16; off; off >>= 1) {
            float od = __shfl_down_sync(0xffffffffu, bd, off);
            int   oi = __shfl_down_sync(0xffffffffu, bi, off);
            if (od > bd || (od == bd && oi < bi)) { bd = od; bi = oi; }
        }
        if (lane == 0) { r_d[wid] = bd; r_i[wid] = bi; }
        __syncthreads();
        if (wid == 0) {
            bd = r_d[lane]; bi = r_i[lane];
#pragma unroll
            for (int off = 16; off; off >>= 1) {
                float od = __shfl_down_sync(0xffffffffu, bd, off);
                int   oi = __shfl_down_sync(0xffffffffu, bi, off);
                if (od > bd || (od == bd && oi < bi)) { bd = od; bi = oi; }
            }
            if (lane == 0) { s_ci = bi; s_c[0] = sx[bi]; s_c[1] = sy[bi]; s_c[2] = sz[bi]; }
        }
        __syncthreads();
    }
}

// ---------------- ball query ----------------
__global__ void ballq_kernel(const float* __restrict__ xyz)
{
    int gw   = (blockIdx.x * blockDim.x + threadIdx.x) >> 5;
    int lane = threadIdx.x & 31;
    int b = gw >> 8, s = gw & 255;
    const float* xb = xyz + (long)b*N_*3;
    float cx = g_newxyz[(b*S_+s)*3 + 0];
    float cy = g_newxyz[(b*S_+s)*3 + 1];
    float cz = g_newxyz[(b*S_+s)*3 + 2];
    int* out = g_idx + (b*S_+s)*KS;
    int count = 0, first = -1;
    for (int base = 0; base < N_; base += 32) {
        int p = base + lane;
        float dx = xb[3*p] - cx, dy = xb[3*p+1] - cy, dz = xb[3*p+2] - cz;
        float d = __fadd_rn(__fadd_rn(__fmul_rn(dx,dx), __fmul_rn(dy,dy)), __fmul_rn(dz,dz));
        bool in = d < 0.09f;
        unsigned mask = __ballot_sync(0xffffffffu, in);
        if (first < 0 && mask) first = base + __ffs(mask) - 1;
        if (in) {
            int slot = count + __popc(mask & ((1u << lane) - 1u));
            if (slot < KS) out[slot] = p;
        }
        count += __popc(mask);
        if (count >= KS) break;
    }
    if (lane < KS && lane >= count) out[lane] = first;
}

// ---------------- gather -> x0 [n][k] fp16, zero-padded K ----------------
__global__ void gather_kernel(const float* __restrict__ xyz, const float* __restrict__ feat)
{
    int w    = (blockIdx.x * blockDim.x + threadIdx.x) >> 5;
    int lane = threadIdx.x & 31;
    int b = w >> 12, n = w & 4095;
    int id = g_idx[b*SK4 + n];
    int s = n >> 4;
    size_t orow = ((size_t)b*SK4 + n) * KPAD;
    const float* fb = feat + (size_t)b*C_*N_ + id;

    float v[10];
#pragma unroll
    for (int it = 0; it < 10; it++) {
        int c = it*32 + lane;
        float val = 0.0f;
        if (it == 0 && lane < 3) {
            val = (xyz[((size_t)b*N_ + id)*3 + c] - g_newxyz[(b*S_+s)*3 + c]) / 0.3f;
        } else if (c < CIN0) {
            val = __ldg(fb + (size_t)(c-3)*N_);
        }
        v[it] = val;
    }
#pragma unroll
    for (int it = 0; it < 10; it++) {
        g_x0[orow + it*32 + lane] = __float2half_rn(v[it]);
    }
}

// ---------------- weight prep ----------------
__global__ void wprep_kernel(const float* __restrict__ W0, const float* __restrict__ W1,
                             const float* __restrict__ W2)
{
    int i = blockIdx.x*256 + threadIdx.x;
    if (i >= 3*MPAD*KPAD) return;
    int l = i / (MPAD*KPAD);
    int r = i % (MPAD*KPAD);
    int m = r / KPAD, k = r % KPAD;
    int cin = (l == 0) ? CIN0 : C_;
    float w = 0.0f;
    if (m < C_ && k < cin) {
        const float* W = (l == 0) ? W0 : ((l == 1) ? W1 : W2);
        w = W[m*cin + k];
    }
    g_w[i] = __float2half_rn(w);
}

// ---------------- fp16 mma GEMM + BN/ReLU (+max) (R10 config: occ2, 2-stage) ----------------
// grid (32 ntiles, 3 mtiles, 16 batches), 256 threads (8 warps: 2m x 4n of 64x32)
__global__ void __launch_bounds__(256, 2) mlp_mma(
    const __half* __restrict__ W, const __half* __restrict__ X,
    __half* __restrict__ O, float* __restrict__ Omax,
    const float* __restrict__ gg, const float* __restrict__ bbp,
    const float* __restrict__ mmp, const float* __restrict__ vvp, int maxmode)
{
    extern __shared__ char dsm_raw[];
    __shared__ float s_sc[128], s_sh[128];

    uint32_t raw = smem_u32(dsm_raw);
    uint32_t dsm = (raw + 1023u) & ~1023u;
    char* dptr = dsm_raw + (dsm - raw);

    int tid = threadIdx.x, lane = tid & 31, wid = tid >> 5;
    int wm = wid & 1, wn = wid >> 1;
    int n0 = blockIdx.x * 128, m0 = blockIdx.y * 128, b = blockIdx.z;

    if (tid < 128) {
        int o = m0 + tid;
        float sc = 0.0f, sh = 0.0f;
        if (o < C_) {
            sc = gg[o] * rsqrtf(vvp[o] + 1e-5f);
            sh = bbp[o] - mmp[o]*sc;
        }
        s_sc[tid] = sc; s_sh[tid] = sh;
    }

    const char* aSrc = (const char*)(W + (size_t)m0 * KPAD);
    const char* bSrc = (const char*)(X + ((size_t)b*SK4 + n0) * KPAD);

    // stage: 2 tiles x (128 rows x 128B) = 32KB; 2 stages
    auto load_stage = [&](int kt, int s) {
        uint32_t sb = dsm + s*32768;
        int k0b = kt * 128;
        const char* srcs[2] = { aSrc, bSrc };
#pragma unroll
        for (int t = 0; t < 2; t++) {
            uint32_t tb = sb + t*16384;
            const char* g = srcs[t] + k0b;
#pragma unroll
            for (int i = 0; i < 4; i++) {
                int idx = tid + i*256;
                int r = idx >> 3, c = idx & 7;
                cp16(tb + sw128(r*128 + c*16), g + (size_t)r*(KPAD*2) + c*16);
            }
        }
        CP_COMMIT();
    };

    load_stage(0, 0);
    load_stage(1, 1);

    float acc[4][4][4];
#pragma unroll
    for (int i = 0; i < 4; i++)
#pragma unroll
        for (int j = 0; j < 4; j++)
#pragma unroll
            for (int r = 0; r < 4; r++) acc[i][j][r] = 0.0f;

    __syncthreads();  // s_sc ready

    for (int kt = 0; kt < KT_; kt++) {
        int s = kt & 1;
        if (kt + 1 < KT_) CP_WAIT(1); else CP_WAIT(0);
        __syncthreads();
        uint32_t sb = dsm + s*32768;
        uint32_t tA = sb, tB = sb + 16384;
#pragma unroll
        for (int ks = 0; ks < 4; ks++) {
            uint32_t bh[4][2];
#pragma unroll
            for (int j = 0; j < 4; j++) {
                uint32_t o = sw128((wn*32 + j*8 + (lane & 7))*128 + ((lane >> 3) & 1)*16 + ks*32);
                ldsm2(bh[j], tB + o);
            }
#pragma unroll
            for (int i = 0; i < 4; i++) {
                uint32_t ah[4];
                uint32_t o = sw128((wm*64 + i*16 + (lane & 15))*128 + (lane >> 4)*16 + ks*32);
                ldsm4(ah, tA + o);
#pragma unroll
                for (int j = 0; j < 4; j++)
                    mma16816(acc[i][j], ah, bh[j]);
            }
        }
        if (kt + 2 < KT_) {
            __syncthreads();
            load_stage(kt + 2, s);
        }
    }

    // ---------------- epilogue ----------------
    if (maxmode) {
#pragma unroll
        for (int i = 0; i < 4; i++) {
#pragma unroll
            for (int r = 0; r < 2; r++) {
                int ml = wm*64 + i*16 + (lane >> 2) + r*8;
                float sc = s_sc[ml], sh = s_sh[ml];
#pragma unroll
                for (int g = 0; g < 2; g++) {
                    float mx = 0.0f;
#pragma unroll
                    for (int jj = 0; jj < 2; jj++) {
                        int j = g*2 + jj;
                        float v0 = fmaxf(fmaf(acc[i][j][r*2],   sc, sh), 0.0f);
                        float v1 = fmaxf(fmaf(acc[i][j][r*2+1], sc, sh), 0.0f);
                        mx = fmaxf(mx, fmaxf(v0, v1));
                    }
                    mx = fmaxf(mx, __shfl_xor_sync(0xffffffffu, mx, 1));
                    mx = fmaxf(mx, __shfl_xor_sync(0xffffffffu, mx, 2));
                    int o = m0 + ml;
                    if ((lane & 3) == 0 && o < C_) {
                        int sgrp = (n0 >> 4) + wn*2 + g;
                        Omax[((size_t)b*C_ + o)*S_ + sgrp] = mx;
                    }
                }
            }
        }
    } else {
        // transpose+store in two half-m chunks via 64x132 smem float buffer
        float* smt = (float*)dptr;
#pragma unroll 1
        for (int h = 0; h < 2; h++) {
            __syncthreads();
            if (wm == h) {
#pragma unroll
                for (int i = 0; i < 4; i++) {
#pragma unroll
                    for (int r = 0; r < 2; r++) {
                        int ml = i*16 + (lane >> 2) + r*8;   // 0..63
                        float sc = s_sc[h*64 + ml], sh = s_sh[h*64 + ml];
#pragma unroll
                        for (int j = 0; j < 4; j++) {
                            int nl = wn*32 + j*8 + (lane & 3)*2;
                            float v0 = fmaxf(fmaf(acc[i][j][r*2],   sc, sh), 0.0f);
                            float v1 = fmaxf(fmaf(acc[i][j][r*2+1], sc, sh), 0.0f);
                            smt[ml*132 + nl]     = v0;
                            smt[ml*132 + nl + 1] = v1;
                        }
                    }
                }
            }
            __syncthreads();
            int n = tid >> 1, half = tid & 1;
            int colg = m0 + h*64 + half*32;
            if (colg < KPAD) {
                size_t doff = ((size_t)b*SK4 + n0 + n)*KPAD + colg;
                uint32_t p[8];
#pragma unroll
                for (int e = 0; e < 8; e++) {
                    float v0 = smt[(half*32 + 2*e)*132 + n];
                    float v1 = smt[(half*32 + 2*e + 1)*132 + n];
                    __half2 hv = __floats2half2_rn(v0, v1);
                    p[e] = *(uint32_t*)&hv;
                }
                *(uint4*)(O + doff)     = make_uint4(p[0], p[1], p[2], p[3]);
                *(uint4*)(O + doff + 8) = make_uint4(p[4], p[5], p[6], p[7]);
                uint32_t q[8];
#pragma unroll
                for (int e = 0; e < 8; e++) {
                    float v0 = smt[(half*32 + 16 + 2*e)*132 + n];
                    float v1 = smt[(half*32 + 16 + 2*e + 1)*132 + n];
                    __half2 hv = __floats2half2_rn(v0, v1);
                    q[e] = *(uint32_t*)&hv;
                }
                *(uint4*)(O + doff + 16) = make_uint4(q[0], q[1], q[2], q[3]);
                *(uint4*)(O + doff + 24) = make_uint4(q[4], q[5], q[6], q[7]);
            }
        }
    }
}

// ---------------- launch ----------------
extern "C" void kernel_launch(void* const* d_in, const int* in_sizes, int n_in,
                              void* d_out, int out_size)
{
    const float* xyz  = (const float*)d_in[0];
    const float* feat = (const float*)d_in[1];
    const float* W0 = (const float*)d_in[2];
    const float* g0 = (const float*)d_in[3];
    const float* b0 = (const float*)d_in[4];
    const float* m0 = (const float*)d_in[5];
    const float* v0 = (const float*)d_in[6];
    const float* W1 = (const float*)d_in[7];
    const float* g1 = (const float*)d_in[8];
    const float* b1 = (const float*)d_in[9];
    const float* m1 = (const float*)d_in[10];
    const float* v1 = (const float*)d_in[11];
    const float* W2 = (const float*)d_in[12];
    const float* g2 = (const float*)d_in[13];
    const float* b2 = (const float*)d_in[14];
    const float* m2 = (const float*)d_in[15];
    const float* v2 = (const float*)d_in[16];

    float* out      = (float*)d_out;
    float* out_xyz  = out;
    float* out_feat = out + B_*S_*3;
    float* out_inds = out + B_*S_*3 + (long)B_*C_*S_;

    cudaFuncSetAttribute(fps_kernel, cudaFuncAttributeMaxDynamicSharedMemorySize,
                         3*N_*(int)sizeof(float));
    cudaFuncSetAttribute(mlp_mma, cudaFuncAttributeMaxDynamicSharedMemorySize, MLP_SMEM);

    wprep_kernel<<<(3*MPAD*KPAD + 255)/256, 256>>>(W0, W1, W2);
    fps_kernel<<<B_, 1024, 3*N_*sizeof(float)>>>(xyz, out_xyz, out_inds);
    ballq_kernel<<<512, 256>>>(xyz);
    gather_kernel<<<8192, 256>>>(xyz, feat);

    __half *w, *x0, *x1;
    cudaGetSymbolAddress((void**)&w,  g_w);
    cudaGetSymbolAddress((void**)&x0, g_x0);
    cudaGetSymbolAddress((void**)&x1, g_x1);

    dim3 grid(32, 3, 16);
    const int L = MPAD*KPAD;
    mlp_mma<<<grid, 256, MLP_SMEM>>>(w,       x0, x1, nullptr, g0, b0, m0, v0, 0);
    mlp_mma<<<grid, 256, MLP_SMEM>>>(w + L,   x1, x0, nullptr, g1, b1, m1, v1, 0);
    mlp_mma<<<grid, 256, MLP_SMEM>>>(w + 2*L, x0, nullptr, out_feat, g2, b2, m2, v2, 1);
}